// round 9
// baseline (speedup 1.0000x reference)
#include <cuda_runtime.h>
#include <math.h>

// Problem constants (fixed by the benchmark problem)
#define BB 8
#define CC 256
#define NN 4096        // H*W = 64*64
#define QKD 32
#define LCC 32
#define OUTC (CC + LCC) // 288

// float4-granularity layout constants
#define MAIN_F4_PER_B 262144   // 256*4096/4 (2^18)
#define OUT_F4_PER_B  294912   // 288*4096/4
#define ROW_F4        1024     // 4096/4 float4 per channel row

// ---------------------------------------------------------------------------
// Fallback (gamma != 0): flash attention for ONE (b,c) output row, using all
// 256 threads of the block. Runs under the kernel's 64-register budget and
// will spill -- acceptable, it is algebraically dead when gamma == 0.
// ---------------------------------------------------------------------------
__device__ __noinline__ void attn_row_fallback(
        const float* __restrict__ x,
        const float* __restrict__ Wq, const float* __restrict__ bq,
        const float* __restrict__ Wk, const float* __restrict__ bk,
        const float* __restrict__ Wv, const float* __restrict__ bv,
        float g, int b, int c, float* __restrict__ dst) {
    __shared__ float ks[256][QKD];   // 32 KB j-tile of k
    __shared__ float vs[256];
    const int t = threadIdx.x;
    const float* xb = x + (long)b * CC * NN;

    for (int i0 = 0; i0 < NN; i0 += 256) {
        const int i = i0 + t;
        float q[QKD];
        #pragma unroll
        for (int d = 0; d < QKD; ++d) q[d] = bq[d];
        for (int cc = 0; cc < CC; ++cc) {
            float xv = xb[(long)cc * NN + i];
            #pragma unroll
            for (int d = 0; d < QKD; ++d) q[d] += Wq[d * CC + cc] * xv;
        }
        float m = -INFINITY, l = 0.0f, acc = 0.0f;
        for (int j0 = 0; j0 < NN; j0 += 256) {
            const int j = j0 + t;
            float kr[QKD];
            #pragma unroll
            for (int d = 0; d < QKD; ++d) kr[d] = bk[d];
            float vv = bv[c];
            for (int cc = 0; cc < CC; ++cc) {
                float xv = xb[(long)cc * NN + j];
                #pragma unroll
                for (int d = 0; d < QKD; ++d) kr[d] += Wk[d * CC + cc] * xv;
                vv += Wv[c * CC + cc] * xv;
            }
            __syncthreads();           // previous tile fully consumed
            #pragma unroll
            for (int d = 0; d < QKD; ++d) ks[t][d] = kr[d];
            vs[t] = vv;
            __syncthreads();
            for (int jj = 0; jj < 256; ++jj) {
                float e = 0.0f;
                #pragma unroll
                for (int d = 0; d < QKD; ++d) e += q[d] * ks[jj][d];
                if (e > m) {
                    float r = expf(m - e);
                    l = l * r + 1.0f;
                    acc = acc * r + vs[jj];
                    m = e;
                } else {
                    float p = expf(e - m);
                    l += p;
                    acc += vs[jj] * p;
                }
            }
        }
        dst[i] = fmaf(g, acc / l, xb[(long)c * NN + i]);
        __syncthreads();
    }
}

// ---------------------------------------------------------------------------
// Single fused kernel. 1152 blocks x 256 threads.
// __launch_bounds__(256, 4): cap regs at 64 so the fast path keeps ~50%
// occupancy; the dead fallback spills to local (harmless).
//   blocks 0..1023: main channels, one 2048-float4 (32 KB) span = 2 rows.
//     gamma==0: pure copy, 8 independent front-batched float4s per thread.
//     gamma!=0: exact flash attention for the 2 rows.
//   blocks 1024..1151: u broadcast, 2 channels per block.
// ---------------------------------------------------------------------------
__global__ __launch_bounds__(256, 4)
void fused_kernel(const float* __restrict__ x,
                  const float* __restrict__ label,
                  const float* __restrict__ Wq, const float* __restrict__ bq,
                  const float* __restrict__ Wk, const float* __restrict__ bk,
                  const float* __restrict__ Wv, const float* __restrict__ bv,
                  const float* __restrict__ gamma,
                  const float* __restrict__ We, const float* __restrict__ be,
                  float* __restrict__ out) {
    const int t = threadIdx.x;
    const float g = __ldg(gamma);

    if (blockIdx.x < 1024) {
        // ---- main-channel region ----
        const int fidx0 = blockIdx.x << 11;          // *2048 float4
        const int b   = fidx0 >> 18;                 // / 262144
        const int off = fidx0 & (MAIN_F4_PER_B - 1);
        float4* dst = (float4*)out + (long)b * OUT_F4_PER_B + off;

        if (g == 0.0f) {
            const float4* src = (const float4*)x + ((b << 18) | off);
            float4 v[8];
            #pragma unroll
            for (int k = 0; k < 8; ++k) v[k] = src[t + (k << 8)];
            #pragma unroll
            for (int k = 0; k < 8; ++k) dst[t + (k << 8)] = v[k];
        } else {
            // two channel rows per block: c0 and c0+1
            const int c0 = off >> 10;                // / ROW_F4
            attn_row_fallback(x, Wq, bq, Wk, bk, Wv, bv, g, b, c0,
                              (float*)dst);
            attn_row_fallback(x, Wq, bq, Wk, bk, Wv, bv, g, b, c0 + 1,
                              (float*)(dst + ROW_F4));
        }
    } else {
        // ---- u broadcast region ----
        const int ub = blockIdx.x - 1024;            // 0..127
        const int b = ub >> 4;                       // 16 blocks per batch
        const int within = (ub & 15) << 11;          // float4 offset in u region
        const int oc0 = within >> 10;                // first of 2 channels

        __shared__ float us[2];
        if (t < 2) {
            const int oc = oc0 + t;
            const float* lb = label + b * LCC;
            float m = -INFINITY;
            #pragma unroll
            for (int l = 0; l < LCC; ++l) m = fmaxf(m, lb[l]);
            float s = 0.0f;
            #pragma unroll
            for (int l = 0; l < LCC; ++l) s += __expf(lb[l] - m);
            const float* wr = We + oc * LCC;
            float acc = 0.0f;
            #pragma unroll
            for (int l = 0; l < LCC; ++l) acc += __expf(lb[l] - m) * wr[l];
            us[t] = acc / s + be[oc];
        }
        __syncthreads();

        float4* dst = (float4*)out + (long)b * OUT_F4_PER_B + MAIN_F4_PER_B + within;
        #pragma unroll
        for (int k = 0; k < 8; ++k) {
            const int p = t + (k << 8);
            const float u = us[p >> 10];
            dst[p] = make_float4(u, u, u, u);
        }
    }
}

// ---------------------------------------------------------------------------
// Launch: ONE graph node.
// Inputs (metadata order): x, label, Wq, bq, Wk, bk, Wv, bv, gamma, We, be
// ---------------------------------------------------------------------------
extern "C" void kernel_launch(void* const* d_in, const int* in_sizes, int n_in,
                              void* d_out, int out_size) {
    const float* x     = (const float*)d_in[0];
    const float* label = (const float*)d_in[1];
    const float* Wq    = (const float*)d_in[2];
    const float* bq    = (const float*)d_in[3];
    const float* Wk    = (const float*)d_in[4];
    const float* bk    = (const float*)d_in[5];
    const float* Wv    = (const float*)d_in[6];
    const float* bv    = (const float*)d_in[7];
    const float* gamma = (const float*)d_in[8];
    const float* We    = (const float*)d_in[9];
    const float* be    = (const float*)d_in[10];
    float* out = (float*)d_out;

    fused_kernel<<<1152, 256>>>(x, label, Wq, bq, Wk, bk, Wv, bv,
                                gamma, We, be, out);
}